// round 1
// baseline (speedup 1.0000x reference)
#include <cuda_runtime.h>
#include <math.h>

#define B 4
#define T 64
#define F 64
#define U 64
#define S 64
#define M 64
#define TF (T*F)

// ---- device scratch (no allocations allowed) ----
__device__ float g_h[B*T*U];        // tanh(inputs@Wk+bk)
__device__ float g_score[B*T*F];    // sum_u tanh(h*out*w_s[S-1])
__device__ int   g_idxt[B*T];       // argmax_f score[t,f]
__device__ float g_ms[B*T*F];       // max_spaces
__device__ float g_logit[B*M];

// =====================================================================
// K1: per (b,t) block. h row, output row, score row, idx_t.
// 256 threads: 64 for h/output, 256 (64f x 4 u-chunks) for score.
// =====================================================================
__global__ void k1_rows(const float* __restrict__ inp,
                        const float* __restrict__ Wk,
                        const float* __restrict__ bk,
                        const float* __restrict__ Wv,
                        const float* __restrict__ bv,
                        const float* __restrict__ w_s,
                        float* __restrict__ outp /* d_out + 2*B*T */) {
    const int bt  = blockIdx.x;          // b*T + t
    const int tid = threadIdx.x;         // 256

    __shared__ float s_in[F];
    __shared__ float s_h[U];
    __shared__ float s_o[F];
    __shared__ float s_part[256];
    __shared__ float s_sc[F];

    if (tid < F) s_in[tid] = inp[bt*F + tid];
    __syncthreads();

    // h[t,u] = tanh(sum_f in[f]*Wk[f,u] + bk[u])
    if (tid < U) {
        float acc = bk[tid];
        #pragma unroll
        for (int f = 0; f < F; ++f)
            acc = fmaf(s_in[f], Wk[f*U + tid], acc);
        float hv = tanhf(acc);
        s_h[tid] = hv;
        g_h[bt*U + tid] = hv;
    }
    __syncthreads();

    // output[t,f] = sum_u h[u]*Wv[u,f] + bv[f]
    if (tid < F) {
        float acc = bv[tid];
        #pragma unroll
        for (int u = 0; u < U; ++u)
            acc = fmaf(s_h[u], Wv[u*F + tid], acc);
        s_o[tid] = acc;
        outp[bt*F + tid] = acc;   // third output, written directly
    }
    __syncthreads();

    // score[t,f] = sum_u tanh(h[u] * out[f] * w_s[S-1])
    {
        const int f = tid & 63;
        const int q = tid >> 6;           // 0..3
        const float c = s_o[f] * w_s[S-1];
        float acc = 0.f;
        #pragma unroll
        for (int u = q*16; u < q*16 + 16; ++u)
            acc += tanhf(s_h[u] * c);
        s_part[tid] = acc;
    }
    __syncthreads();

    if (tid < F) {
        float sc = s_part[tid] + s_part[64 + tid] + s_part[128 + tid] + s_part[192 + tid];
        s_sc[tid] = sc;
        g_score[bt*F + tid] = sc;
    }
    __syncthreads();

    // idx_t[t] = argmax_f score (first index on ties, ascending strict >)
    if (tid == 0) {
        float best = s_sc[0]; int bi = 0;
        #pragma unroll
        for (int f = 1; f < F; ++f) {
            float v = s_sc[f];
            if (v > best) { best = v; bi = f; }
        }
        g_idxt[bt] = bi;
    }
}

// =====================================================================
// K2: per batch. idx_f, wmax/wmin, amax/amin, then max_spaces via
// monotone-tanh corner-max identity.
// =====================================================================
__global__ void k2_maxspaces(const float* __restrict__ w_s,
                             const float* __restrict__ outp) {
    const int b   = blockIdx.x;
    const int tid = threadIdx.x;   // 256

    __shared__ float s_score[TF];
    __shared__ float s_h[T*U];
    __shared__ int   s_idxt[T];
    __shared__ int   s_idxf[F];
    __shared__ float s_amax[T], s_amin[T];
    __shared__ float s_wmax, s_wmin;

    for (int i = tid; i < TF; i += 256) {
        s_score[i] = g_score[b*TF + i];
        s_h[i]     = g_h[b*T*U + i];
    }
    if (tid < T) s_idxt[tid] = g_idxt[b*T + tid];
    __syncthreads();

    if (tid < F) {
        // idx_f[f] = argmax_t score[t,f] (first index on ties)
        const int f = tid;
        float best = s_score[f]; int bi = 0;
        #pragma unroll 4
        for (int t = 1; t < T; ++t) {
            float v = s_score[t*F + f];
            if (v > best) { best = v; bi = t; }
        }
        s_idxf[f] = bi;
    } else if (tid < 128) {
        // amax/amin[t] over h[t, idx_t[i]]
        const int t = tid - 64;
        float mx = -INFINITY, mn = INFINITY;
        #pragma unroll 4
        for (int i = 0; i < T; ++i) {
            float v = s_h[t*U + s_idxt[i]];
            mx = fmaxf(mx, v);
            mn = fminf(mn, v);
        }
        s_amax[t] = mx; s_amin[t] = mn;
    }
    __syncthreads();

    if (tid < 32) {
        float w0 = w_s[s_idxf[tid]];
        float w1 = w_s[s_idxf[tid + 32]];
        float mx = fmaxf(w0, w1), mn = fminf(w0, w1);
        #pragma unroll
        for (int o = 16; o; o >>= 1) {
            mx = fmaxf(mx, __shfl_xor_sync(0xffffffffu, mx, o));
            mn = fminf(mn, __shfl_xor_sync(0xffffffffu, mn, o));
        }
        if (tid == 0) { s_wmax = mx; s_wmin = mn; }
    }
    __syncthreads();

    const float wmax = s_wmax, wmin = s_wmin;
    for (int i = tid; i < TF; i += 256) {
        const int t  = i >> 6;
        const float c   = outp[b*TF + i];
        const float amx = s_amax[t], amn = s_amin[t];
        float m = fmaxf(fmaxf(amx*wmax*c, amx*wmin*c),
                        fmaxf(amn*wmax*c, amn*wmin*c));
        g_ms[b*TF + i] = tanhf(m);
    }
}

// =====================================================================
// K3: logits[b,m] = dot(ms[b], mem_keys[m])  — one block per (b,m)
// =====================================================================
__global__ void k3_logits(const float* __restrict__ mem_keys) {
    const int b = blockIdx.x >> 6;
    const int m = blockIdx.x & 63;
    const int tid = threadIdx.x;   // 128

    const float* __restrict__ ms = g_ms + b*TF;
    const float* __restrict__ mk = mem_keys + m*TF;

    float acc = 0.f;
    #pragma unroll 8
    for (int i = tid; i < TF; i += 128)
        acc = fmaf(ms[i], mk[i], acc);

    __shared__ float s_r[4];
    #pragma unroll
    for (int o = 16; o; o >>= 1) acc += __shfl_xor_sync(0xffffffffu, acc, o);
    if ((tid & 31) == 0) s_r[tid >> 5] = acc;
    __syncthreads();
    if (tid == 0) g_logit[b*M + m] = s_r[0] + s_r[1] + s_r[2] + s_r[3];
}

// =====================================================================
// K4: per batch. softmax, targets, importance, dist. 64 threads.
// =====================================================================
__global__ void k4_head(const float* __restrict__ inp,
                        const float* __restrict__ mem_vals,
                        float* __restrict__ d_out) {
    const int b = blockIdx.x;
    const int tid = threadIdx.x;   // 64

    __shared__ float s_tmp[M];
    __shared__ float s_attn[M];
    __shared__ float s_tgt[F];
    __shared__ float s_max, s_sum;

    const float l = g_logit[b*M + tid];
    s_tmp[tid] = l;
    __syncthreads();
    if (tid == 0) {
        float mx = s_tmp[0];
        #pragma unroll
        for (int i = 1; i < M; ++i) mx = fmaxf(mx, s_tmp[i]);
        s_max = mx;
    }
    __syncthreads();
    const float e = expf(l - s_max);
    s_tmp[tid] = e;
    __syncthreads();
    if (tid == 0) {
        float s = 0.f;
        #pragma unroll
        for (int i = 0; i < M; ++i) s += s_tmp[i];
        s_sum = s;
    }
    __syncthreads();
    const float attn = e / s_sum;
    s_attn[tid] = attn;
    const float imp = 1.0f / s_sum;   // max attn = exp(0)/sum
    __syncthreads();

    // targets[f] = sum_m attn[m]*mem_vals[m,f]
    {
        float acc = 0.f;
        #pragma unroll
        for (int mm = 0; mm < M; ++mm)
            acc = fmaf(s_attn[mm], mem_vals[mm*F + tid], acc);
        s_tgt[tid] = acc;
    }
    __syncthreads();

    // dist[t] = 0.5 - clip(0.2*||inp[t]-tgt|| + 0.5, 0, 1)
    {
        const int t = tid;
        float a2 = 0.f;
        #pragma unroll
        for (int f = 0; f < F; ++f) {
            float d = inp[(b*T + t)*F + f] - s_tgt[f];
            a2 = fmaf(d, d, a2);
        }
        float nrm = sqrtf(a2);
        float hs = fminf(fmaxf(0.2f*nrm + 0.5f, 0.f), 1.f);
        d_out[b*T + t]         = 0.5f - hs;   // dist
        d_out[B*T + b*T + t]   = imp;         // importances
    }
}

// =====================================================================
extern "C" void kernel_launch(void* const* d_in, const int* in_sizes, int n_in,
                              void* d_out, int out_size) {
    const float* inp      = (const float*)d_in[0];  // [B,T,F]
    const float* Wk       = (const float*)d_in[1];  // [F,U]
    const float* bk       = (const float*)d_in[2];  // [U]
    const float* Wv       = (const float*)d_in[3];  // [U,F]
    const float* bv       = (const float*)d_in[4];  // [F]
    const float* w_s      = (const float*)d_in[5];  // [S]
    const float* mem_keys = (const float*)d_in[6];  // [M, T*F]
    const float* mem_vals = (const float*)d_in[7];  // [M, F]

    float* out = (float*)d_out;
    float* outp = out + 2*B*T;   // "output" tensor region

    k1_rows<<<B*T, 256>>>(inp, Wk, bk, Wv, bv, w_s, outp);
    k2_maxspaces<<<B, 256>>>(w_s, outp);
    k3_logits<<<B*M, 128>>>(mem_keys);
    k4_head<<<B, 64>>>(inp, mem_vals, out);
}

// round 2
// speedup vs baseline: 1.4018x; 1.4018x over previous
#include <cuda_runtime.h>
#include <math.h>
#include <stdint.h>

#define B 4
#define T 64
#define F 64
#define U 64
#define S 64
#define M 64
#define TF (T*F)
#define CPB 4          // CTAs per batch (cluster size)
#define MPC (M/CPB)    // 16 logits per CTA
#define TPC (T/CPB)    // 16 dist rows per CTA

// ---- device scratch (no allocations allowed) ----
__device__ float g_h[B*T*U];        // tanh(inputs@Wk+bk)
__device__ float g_score[B*T*F];    // sum_u tanh(h*out*w_s[S-1])
__device__ int   g_idxt[B*T];       // argmax_f score[t,f]

// Fast accurate-enough tanh: exact identity, approx exp/div (MUFU).
// Abs error ~1e-7, relative ~1e-6 for |x|>~1e-1. Safe for argmax stability.
__device__ __forceinline__ float fast_tanh(float x) {
    float e = __expf(2.0f * x);                  // MUFU.EX2 path; inf for large x -> +1, 0 -> -1
    return 1.0f - __fdividef(2.0f, e + 1.0f);
}

__device__ __forceinline__ uint32_t smem_u32(const void* p) {
    uint32_t a;
    asm("{ .reg .u64 t; cvta.to.shared.u64 t, %1; cvt.u32.u64 %0, t; }" : "=r"(a) : "l"(p));
    return a;
}

__device__ __forceinline__ void st_cluster_f32(uint32_t saddr, int rank, float v) {
    uint32_t r;
    asm volatile("mapa.shared::cluster.u32 %0, %1, %2;" : "=r"(r) : "r"(saddr), "r"(rank));
    asm volatile("st.shared::cluster.f32 [%0], %1;" :: "r"(r), "f"(v) : "memory");
}

// =====================================================================
// K1: per (b,t) block. h row, output row, score row, idx_t.
// =====================================================================
__global__ void __launch_bounds__(256) k1_rows(
        const float* __restrict__ inp,
        const float* __restrict__ Wk,
        const float* __restrict__ bk,
        const float* __restrict__ Wv,
        const float* __restrict__ bv,
        const float* __restrict__ w_s,
        float* __restrict__ outp /* d_out + 2*B*T */) {
    const int bt  = blockIdx.x;
    const int tid = threadIdx.x;

    __shared__ float s_in[F];
    __shared__ float s_h[U];
    __shared__ float s_o[F];
    __shared__ float s_part[256];
    __shared__ float s_sc[F];

    if (tid < F) s_in[tid] = inp[bt*F + tid];
    __syncthreads();

    if (tid < U) {
        float acc = bk[tid];
        #pragma unroll
        for (int f = 0; f < F; ++f)
            acc = fmaf(s_in[f], Wk[f*U + tid], acc);
        float hv = fast_tanh(acc);
        s_h[tid] = hv;
        g_h[bt*U + tid] = hv;
    }
    __syncthreads();

    if (tid < F) {
        float acc = bv[tid];
        #pragma unroll
        for (int u = 0; u < U; ++u)
            acc = fmaf(s_h[u], Wv[u*F + tid], acc);
        s_o[tid] = acc;
        outp[bt*F + tid] = acc;
    }
    __syncthreads();

    // score[t,f] = sum_u tanh(h[u] * out[f] * w_s[S-1])
    {
        const int f = tid & 63;
        const int q = tid >> 6;
        const float c = s_o[f] * w_s[S-1];
        float acc = 0.f;
        #pragma unroll
        for (int u = q*16; u < q*16 + 16; ++u)
            acc += fast_tanh(s_h[u] * c);
        s_part[tid] = acc;
    }
    __syncthreads();

    if (tid < F) {
        float sc = s_part[tid] + s_part[64 + tid] + s_part[128 + tid] + s_part[192 + tid];
        s_sc[tid] = sc;
        g_score[bt*F + tid] = sc;
    }
    __syncthreads();

    if (tid == 0) {
        float best = s_sc[0]; int bi = 0;
        #pragma unroll
        for (int f = 1; f < F; ++f) {
            float v = s_sc[f];
            if (v > best) { best = v; bi = f; }
        }
        g_idxt[bt] = bi;
    }
}

// =====================================================================
// KB: fused tail. Cluster of 4 CTAs per batch, 512 threads each.
// Each CTA: idx_f, amax/amin, wmax/wmin, ms (smem), 16 logits,
// DSMEM logit exchange, softmax, targets, dist for its 16 t's.
// =====================================================================
__global__ void __launch_bounds__(512) __cluster_dims__(CPB, 1, 1) kb_fused(
        const float* __restrict__ inp,
        const float* __restrict__ w_s,
        const float* __restrict__ mem_keys,
        const float* __restrict__ mem_vals,
        const float* __restrict__ outp,
        float* __restrict__ d_out) {
    const int b    = blockIdx.x / CPB;
    const int r    = blockIdx.x % CPB;
    const int tid  = threadIdx.x;
    const int w    = tid >> 5;
    const int lane = tid & 31;

    __shared__ __align__(16) float s_buf[65*64];  // score (padded), then ms (contiguous 4096)
    __shared__ float s_h[65*64];                  // h (padded)
    __shared__ int   s_idxt[T];
    __shared__ int   s_idxf[F];
    __shared__ float s_amax[T], s_amin[T];
    __shared__ float s_wmm[2];
    __shared__ float s_logit[M];
    __shared__ float s_attn[M];
    __shared__ float s_tgt[F];
    __shared__ float s_red[4];

    // Load score + h with bank-conflict padding
    for (int i = tid; i < TF; i += 512) {
        const int t = i >> 6, f = i & 63;
        s_buf[t*65 + f] = g_score[b*TF + i];
        s_h[t*65 + f]   = g_h[b*TF + i];
    }
    if (tid < T) s_idxt[tid] = g_idxt[b*T + tid];
    __syncthreads();

    if (tid < F) {
        // idx_f[f] = argmax_t score[t,f] (first index on ties)
        const int f = tid;
        float best = s_buf[f]; int bi = 0;
        #pragma unroll 4
        for (int t = 1; t < T; ++t) {
            float v = s_buf[t*65 + f];
            if (v > best) { best = v; bi = t; }
        }
        s_idxf[f] = bi;
    } else if (tid < 128) {
        const int t = tid - 64;
        float mx = -INFINITY, mn = INFINITY;
        #pragma unroll 4
        for (int i = 0; i < T; ++i) {
            float v = s_h[t*65 + s_idxt[i]];
            mx = fmaxf(mx, v);
            mn = fminf(mn, v);
        }
        s_amax[t] = mx; s_amin[t] = mn;
    }
    __syncthreads();

    if (tid < 32) {
        float w0 = w_s[s_idxf[tid]];
        float w1 = w_s[s_idxf[tid + 32]];
        float mx = fmaxf(w0, w1), mn = fminf(w0, w1);
        #pragma unroll
        for (int o = 16; o; o >>= 1) {
            mx = fmaxf(mx, __shfl_xor_sync(0xffffffffu, mx, o));
            mn = fminf(mn, __shfl_xor_sync(0xffffffffu, mn, o));
        }
        if (tid == 0) { s_wmm[0] = mx; s_wmm[1] = mn; }
    }
    __syncthreads();

    // ms into s_buf[0..4096) (score no longer needed)
    {
        const float wmax = s_wmm[0], wmin = s_wmm[1];
        for (int i = tid; i < TF; i += 512) {
            const int t = i >> 6;
            const float c   = outp[b*TF + i];
            const float amx = s_amax[t], amn = s_amin[t];
            float m = fmaxf(fmaxf(amx*wmax*c, amx*wmin*c),
                            fmaxf(amn*wmax*c, amn*wmin*c));
            s_buf[i] = fast_tanh(m);
        }
    }
    __syncthreads();

    // logits: warp w computes m = r*16 + w, broadcast to all cluster CTAs
    {
        const int m = r*MPC + w;
        const float4* __restrict__ key = (const float4*)(mem_keys + m*TF);
        const float4* __restrict__ ms4 = (const float4*)s_buf;
        float a0 = 0.f, a1 = 0.f, a2 = 0.f, a3 = 0.f;
        #pragma unroll
        for (int j = 0; j < 32; ++j) {
            float4 kk = key[lane + j*32];
            float4 mm = ms4[lane + j*32];
            a0 = fmaf(kk.x, mm.x, a0);
            a1 = fmaf(kk.y, mm.y, a1);
            a2 = fmaf(kk.z, mm.z, a2);
            a3 = fmaf(kk.w, mm.w, a3);
        }
        float acc = (a0 + a1) + (a2 + a3);
        #pragma unroll
        for (int o = 16; o; o >>= 1)
            acc += __shfl_xor_sync(0xffffffffu, acc, o);
        if (lane == 0) {
            uint32_t sl = smem_u32(&s_logit[m]);
            #pragma unroll
            for (int tr = 0; tr < CPB; ++tr)
                st_cluster_f32(sl, tr, acc);
        }
    }

    // cluster barrier: all 64 logits visible in every CTA
    asm volatile("barrier.cluster.arrive.aligned;" ::: "memory");
    asm volatile("barrier.cluster.wait.aligned;" ::: "memory");

    // softmax over 64 logits (warps 0,1)
    float l = 0.f, e = 0.f;
    if (tid < M) {
        l = s_logit[tid];
        float mx = l;
        #pragma unroll
        for (int o = 16; o; o >>= 1)
            mx = fmaxf(mx, __shfl_xor_sync(0xffffffffu, mx, o));
        if (lane == 0) s_red[w] = mx;
    }
    __syncthreads();
    const float gmax = fmaxf(s_red[0], s_red[1]);
    if (tid < M) {
        e = __expf(l - gmax);
        float s = e;
        #pragma unroll
        for (int o = 16; o; o >>= 1)
            s += __shfl_xor_sync(0xffffffffu, s, o);
        if (lane == 0) s_red[2 + w] = s;
    }
    __syncthreads();
    const float gsum = s_red[2] + s_red[3];
    const float imp  = 1.0f / gsum;                 // max(attn) = exp(0)/sum
    if (tid < M) s_attn[tid] = e / gsum;
    __syncthreads();

    // targets[f] = sum_m attn[m]*mem_vals[m,f]
    if (tid < F) {
        float acc = 0.f;
        #pragma unroll
        for (int mm = 0; mm < M; ++mm)
            acc = fmaf(s_attn[mm], mem_vals[mm*F + tid], acc);
        s_tgt[tid] = acc;
    }
    __syncthreads();

    // dist: warp w handles t = r*16 + w
    {
        const int t = r*TPC + w;
        const float* __restrict__ irow = inp + (b*T + t)*F;
        float d0 = irow[lane]      - s_tgt[lane];
        float d1 = irow[lane + 32] - s_tgt[lane + 32];
        float a2 = d0*d0 + d1*d1;
        #pragma unroll
        for (int o = 16; o; o >>= 1)
            a2 += __shfl_xor_sync(0xffffffffu, a2, o);
        if (lane == 0) {
            float nrm = sqrtf(a2);
            float hs  = fminf(fmaxf(0.2f*nrm + 0.5f, 0.f), 1.f);
            d_out[b*T + t]       = 0.5f - hs;  // dist
            d_out[B*T + b*T + t] = imp;        // importances
        }
    }
}

// =====================================================================
extern "C" void kernel_launch(void* const* d_in, const int* in_sizes, int n_in,
                              void* d_out, int out_size) {
    const float* inp      = (const float*)d_in[0];  // [B,T,F]
    const float* Wk       = (const float*)d_in[1];  // [F,U]
    const float* bk       = (const float*)d_in[2];  // [U]
    const float* Wv       = (const float*)d_in[3];  // [U,F]
    const float* bv       = (const float*)d_in[4];  // [F]
    const float* w_s      = (const float*)d_in[5];  // [S]
    const float* mem_keys = (const float*)d_in[6];  // [M, T*F]
    const float* mem_vals = (const float*)d_in[7];  // [M, F]

    float* out  = (float*)d_out;
    float* outp = out + 2*B*T;   // "output" tensor region

    k1_rows<<<B*T, 256>>>(inp, Wk, bk, Wv, bv, w_s, outp);
    kb_fused<<<B*CPB, 512>>>(inp, w_s, mem_keys, mem_vals, outp, out);
}

// round 3
// speedup vs baseline: 1.4125x; 1.0076x over previous
#include <cuda_runtime.h>
#include <math.h>
#include <stdint.h>

#define B 4
#define T 64
#define F 64
#define U 64
#define S 64
#define M 64
#define TF (T*F)
#define CPB 4          // CTAs per batch (cluster size)
#define MPC (M/CPB)    // 16 logits per CTA
#define TPC (T/CPB)    // 16 dist rows per CTA

// ---- device scratch (no allocations allowed) ----
__device__ float g_h[B*T*U];        // tanh(inputs@Wk+bk)
__device__ float g_score[B*T*F];    // sum_u tanh(h*out*w_s[S-1])
__device__ int   g_idxt[B*T];       // argmax_f score[t,f]

// Accurate-enough tanh for value paths (h, ms): abs err ~1e-7.
__device__ __forceinline__ float fast_tanh(float x) {
    float e = __expf(2.0f * x);
    return 1.0f - __fdividef(2.0f, e + 1.0f);
}

// Single-MUFU tanh for the argmax-only score path (abs err ~5.4e-4).
__device__ __forceinline__ float tanh_mufu(float x) {
    float y;
    asm("tanh.approx.f32 %0, %1;" : "=f"(y) : "f"(x));
    return y;
}

__device__ __forceinline__ uint32_t smem_u32(const void* p) {
    uint32_t a;
    asm("{ .reg .u64 t; cvta.to.shared.u64 t, %1; cvt.u32.u64 %0, t; }" : "=r"(a) : "l"(p));
    return a;
}

__device__ __forceinline__ void st_cluster_f32(uint32_t saddr, int rank, float v) {
    uint32_t r;
    asm volatile("mapa.shared::cluster.u32 %0, %1, %2;" : "=r"(r) : "r"(saddr), "r"(rank));
    asm volatile("st.shared::cluster.f32 [%0], %1;" :: "r"(r), "f"(v) : "memory");
}

// =====================================================================
// K1: per (b,t) block. h row, output row, score row, idx_t.
// =====================================================================
__global__ void __launch_bounds__(256) k1_rows(
        const float* __restrict__ inp,
        const float* __restrict__ Wk,
        const float* __restrict__ bk,
        const float* __restrict__ Wv,
        const float* __restrict__ bv,
        const float* __restrict__ w_s,
        float* __restrict__ outp /* d_out + 2*B*T */) {
    const int bt  = blockIdx.x;
    const int tid = threadIdx.x;

    __shared__ float s_in[F];
    __shared__ float s_h[U];
    __shared__ float s_o[F];
    __shared__ float s_part[256];
    __shared__ float s_sc[F];

    if (tid < F) s_in[tid] = inp[bt*F + tid];
    __syncthreads();

    if (tid < U) {
        float acc = bk[tid];
        #pragma unroll
        for (int f = 0; f < F; ++f)
            acc = fmaf(s_in[f], Wk[f*U + tid], acc);
        float hv = fast_tanh(acc);          // accurate: feeds output GEMM
        s_h[tid] = hv;
        g_h[bt*U + tid] = hv;
    }
    __syncthreads();

    if (tid < F) {
        float acc = bv[tid];
        #pragma unroll
        for (int u = 0; u < U; ++u)
            acc = fmaf(s_h[u], Wv[u*F + tid], acc);
        s_o[tid] = acc;
        outp[bt*F + tid] = acc;
    }
    __syncthreads();

    // score[t,f] = sum_u tanh(h[u] * out[f] * w_s[S-1])   (argmax-only -> MUFU.TANH)
    {
        const int f = tid & 63;
        const int q = tid >> 6;
        const float c = s_o[f] * w_s[S-1];
        float acc = 0.f;
        #pragma unroll
        for (int u = q*16; u < q*16 + 16; ++u)
            acc += tanh_mufu(s_h[u] * c);
        s_part[tid] = acc;
    }
    __syncthreads();

    if (tid < F) {
        float sc = s_part[tid] + s_part[64 + tid] + s_part[128 + tid] + s_part[192 + tid];
        s_sc[tid] = sc;
        g_score[bt*F + tid] = sc;
    }
    __syncthreads();

    if (tid == 0) {
        float best = s_sc[0]; int bi = 0;
        #pragma unroll
        for (int f = 1; f < F; ++f) {
            float v = s_sc[f];
            if (v > best) { best = v; bi = f; }
        }
        g_idxt[bt] = bi;
    }
}

// =====================================================================
// KB: fused tail. Cluster of 4 CTAs per batch, 512 threads each.
// =====================================================================
__global__ void __launch_bounds__(512) __cluster_dims__(CPB, 1, 1) kb_fused(
        const float* __restrict__ inp,
        const float* __restrict__ w_s,
        const float* __restrict__ mem_keys,
        const float* __restrict__ mem_vals,
        const float* __restrict__ outp,
        float* __restrict__ d_out) {
    const int b    = blockIdx.x / CPB;
    const int r    = blockIdx.x % CPB;
    const int tid  = threadIdx.x;
    const int w    = tid >> 5;
    const int lane = tid & 31;

    __shared__ __align__(16) float s_buf[65*64];  // score (padded), then ms (contiguous 4096)
    __shared__ float s_h[65*64];                  // h (padded)
    __shared__ int   s_idxt[T];
    __shared__ int   s_idxf[F];
    __shared__ float s_amax[T], s_amin[T];
    __shared__ float s_wmm[2];
    __shared__ float s_logit[M];
    __shared__ float s_attn[M];
    __shared__ float s_tgt[F];
    __shared__ float s_red[4];

    for (int i = tid; i < TF; i += 512) {
        const int t = i >> 6, f = i & 63;
        s_buf[t*65 + f] = g_score[b*TF + i];
        s_h[t*65 + f]   = g_h[b*TF + i];
    }
    if (tid < T) s_idxt[tid] = g_idxt[b*T + tid];
    __syncthreads();

    if (tid < F) {
        const int f = tid;
        float best = s_buf[f]; int bi = 0;
        #pragma unroll 4
        for (int t = 1; t < T; ++t) {
            float v = s_buf[t*65 + f];
            if (v > best) { best = v; bi = t; }
        }
        s_idxf[f] = bi;
    } else if (tid < 128) {
        const int t = tid - 64;
        float mx = -INFINITY, mn = INFINITY;
        #pragma unroll 4
        for (int i = 0; i < T; ++i) {
            float v = s_h[t*65 + s_idxt[i]];
            mx = fmaxf(mx, v);
            mn = fminf(mn, v);
        }
        s_amax[t] = mx; s_amin[t] = mn;
    }
    __syncthreads();

    if (tid < 32) {
        float w0 = w_s[s_idxf[tid]];
        float w1 = w_s[s_idxf[tid + 32]];
        float mx = fmaxf(w0, w1), mn = fminf(w0, w1);
        #pragma unroll
        for (int o = 16; o; o >>= 1) {
            mx = fmaxf(mx, __shfl_xor_sync(0xffffffffu, mx, o));
            mn = fminf(mn, __shfl_xor_sync(0xffffffffu, mn, o));
        }
        if (tid == 0) { s_wmm[0] = mx; s_wmm[1] = mn; }
    }
    __syncthreads();

    {
        const float wmax = s_wmm[0], wmin = s_wmm[1];
        for (int i = tid; i < TF; i += 512) {
            const int t = i >> 6;
            const float c   = outp[b*TF + i];
            const float amx = s_amax[t], amn = s_amin[t];
            float m = fmaxf(fmaxf(amx*wmax*c, amx*wmin*c),
                            fmaxf(amn*wmax*c, amn*wmin*c));
            s_buf[i] = fast_tanh(m);       // accurate: feeds logits/importances
        }
    }
    __syncthreads();

    {
        const int m = r*MPC + w;
        const float4* __restrict__ key = (const float4*)(mem_keys + m*TF);
        const float4* __restrict__ ms4 = (const float4*)s_buf;
        float a0 = 0.f, a1 = 0.f, a2 = 0.f, a3 = 0.f;
        #pragma unroll
        for (int j = 0; j < 32; ++j) {
            float4 kk = key[lane + j*32];
            float4 mm = ms4[lane + j*32];
            a0 = fmaf(kk.x, mm.x, a0);
            a1 = fmaf(kk.y, mm.y, a1);
            a2 = fmaf(kk.z, mm.z, a2);
            a3 = fmaf(kk.w, mm.w, a3);
        }
        float acc = (a0 + a1) + (a2 + a3);
        #pragma unroll
        for (int o = 16; o; o >>= 1)
            acc += __shfl_xor_sync(0xffffffffu, acc, o);
        if (lane == 0) {
            uint32_t sl = smem_u32(&s_logit[m]);
            #pragma unroll
            for (int tr = 0; tr < CPB; ++tr)
                st_cluster_f32(sl, tr, acc);
        }
    }

    asm volatile("barrier.cluster.arrive.aligned;" ::: "memory");
    asm volatile("barrier.cluster.wait.aligned;" ::: "memory");

    float l = 0.f, e = 0.f;
    if (tid < M) {
        l = s_logit[tid];
        float mx = l;
        #pragma unroll
        for (int o = 16; o; o >>= 1)
            mx = fmaxf(mx, __shfl_xor_sync(0xffffffffu, mx, o));
        if (lane == 0) s_red[w] = mx;
    }
    __syncthreads();
    const float gmax = fmaxf(s_red[0], s_red[1]);
    if (tid < M) {
        e = __expf(l - gmax);
        float s = e;
        #pragma unroll
        for (int o = 16; o; o >>= 1)
            s += __shfl_xor_sync(0xffffffffu, s, o);
        if (lane == 0) s_red[2 + w] = s;
    }
    __syncthreads();
    const float gsum = s_red[2] + s_red[3];
    const float imp  = 1.0f / gsum;
    if (tid < M) s_attn[tid] = e / gsum;
    __syncthreads();

    if (tid < F) {
        float acc = 0.f;
        #pragma unroll
        for (int mm = 0; mm < M; ++mm)
            acc = fmaf(s_attn[mm], mem_vals[mm*F + tid], acc);
        s_tgt[tid] = acc;
    }
    __syncthreads();

    {
        const int t = r*TPC + w;
        const float* __restrict__ irow = inp + (b*T + t)*F;
        float d0 = irow[lane]      - s_tgt[lane];
        float d1 = irow[lane + 32] - s_tgt[lane + 32];
        float a2 = d0*d0 + d1*d1;
        #pragma unroll
        for (int o = 16; o; o >>= 1)
            a2 += __shfl_xor_sync(0xffffffffu, a2, o);
        if (lane == 0) {
            float nrm = sqrtf(a2);
            float hs  = fminf(fmaxf(0.2f*nrm + 0.5f, 0.f), 1.f);
            d_out[b*T + t]       = 0.5f - hs;
            d_out[B*T + b*T + t] = imp;
        }
    }
}

// =====================================================================
extern "C" void kernel_launch(void* const* d_in, const int* in_sizes, int n_in,
                              void* d_out, int out_size) {
    const float* inp      = (const float*)d_in[0];  // [B,T,F]
    const float* Wk       = (const float*)d_in[1];  // [F,U]
    const float* bk       = (const float*)d_in[2];  // [U]
    const float* Wv       = (const float*)d_in[3];  // [U,F]
    const float* bv       = (const float*)d_in[4];  // [F]
    const float* w_s      = (const float*)d_in[5];  // [S]
    const float* mem_keys = (const float*)d_in[6];  // [M, T*F]
    const float* mem_vals = (const float*)d_in[7];  // [M, F]

    float* out  = (float*)d_out;
    float* outp = out + 2*B*T;   // "output" tensor region

    k1_rows<<<B*T, 256>>>(inp, Wk, bk, Wv, bv, w_s, outp);
    kb_fused<<<B*CPB, 512>>>(inp, w_s, mem_keys, mem_vals, outp, out);
}

// round 4
// speedup vs baseline: 2.3258x; 1.6466x over previous
#include <cuda_runtime.h>
#include <math.h>
#include <stdint.h>

#define B 4
#define T 64
#define F 64
#define U 64
#define M 64
#define TF (T*F)
#define CPB 8          // CTAs per cluster (one cluster per batch)
#define RPC (T/CPB)    // 8 rows (t) per CTA
#define NTH 256

// Accurate tanh for value paths (h, ms): abs err ~1e-7.
__device__ __forceinline__ float fast_tanh(float x) {
    float e = __expf(2.0f * x);
    return 1.0f - __fdividef(2.0f, e + 1.0f);
}
// Single-MUFU tanh for the argmax-only score path.
__device__ __forceinline__ float tanh_mufu(float x) {
    float y; asm("tanh.approx.f32 %0, %1;" : "=f"(y) : "f"(x)); return y;
}
__device__ __forceinline__ uint32_t smem_u32(const void* p) {
    uint32_t a;
    asm("{ .reg .u64 t; cvta.to.shared.u64 t, %1; cvt.u32.u64 %0, t; }" : "=r"(a) : "l"(p));
    return a;
}
__device__ __forceinline__ void stc_f32(uint32_t saddr, int rank, float v) {
    uint32_t rr;
    asm volatile("mapa.shared::cluster.u32 %0, %1, %2;" : "=r"(rr) : "r"(saddr), "r"(rank));
    asm volatile("st.shared::cluster.f32 [%0], %1;" :: "r"(rr), "f"(v) : "memory");
}
__device__ __forceinline__ void stc_s32(uint32_t saddr, int rank, int v) {
    uint32_t rr;
    asm volatile("mapa.shared::cluster.u32 %0, %1, %2;" : "=r"(rr) : "r"(saddr), "r"(rank));
    asm volatile("st.shared::cluster.u32 [%0], %1;" :: "r"(rr), "r"(v) : "memory");
}
__device__ __forceinline__ void stc_u64(uint32_t saddr, int rank, unsigned long long v) {
    uint32_t rr;
    asm volatile("mapa.shared::cluster.u32 %0, %1, %2;" : "=r"(rr) : "r"(saddr), "r"(rank));
    asm volatile("st.shared::cluster.u64 [%0], %1;" :: "r"(rr), "l"(v) : "memory");
}
__device__ __forceinline__ void cluster_barrier() {
    asm volatile("barrier.cluster.arrive.aligned;" ::: "memory");
    asm volatile("barrier.cluster.wait.aligned;" ::: "memory");
}

// =====================================================================
// Single fused kernel: cluster of 8 CTAs per batch, 8 warps per CTA,
// warp w owns global row t = rank*8 + w.
// =====================================================================
__global__ void __launch_bounds__(NTH) __cluster_dims__(CPB, 1, 1)
fused_all(const float* __restrict__ inp,
          const float* __restrict__ Wk,
          const float* __restrict__ bk,
          const float* __restrict__ Wv,
          const float* __restrict__ bv,
          const float* __restrict__ w_s,
          const float* __restrict__ mem_keys,
          const float* __restrict__ mem_vals,
          float* __restrict__ d_out) {
    const int b    = blockIdx.x / CPB;
    const int r    = blockIdx.x % CPB;
    const int tid  = threadIdx.x;
    const int w    = tid >> 5;
    const int lane = tid & 31;

    __shared__ float s_in[RPC][F];
    __shared__ float s_h [RPC][U];
    __shared__ float s_o [RPC][F];
    __shared__ float s_sc[RPC][F];
    __shared__ __align__(16) float s_ms[RPC*F];
    __shared__ unsigned long long s_cand[CPB][F];  // [rank][f] packed (val<<32 | t)
    __shared__ int   s_idxt[T];
    __shared__ float s_lp[CPB][M];                 // [rank][m] logit partials
    __shared__ float s_tmp[M];
    __shared__ float s_attn[M];
    __shared__ float s_tgt[F];
    __shared__ float s_amax[RPC], s_amin[RPC];
    __shared__ float s_wred[2][2];
    __shared__ float s_red[4];
    __shared__ float s_wmm[2];

    const float wlast = __ldg(w_s + 63);   // w_s[S-1]
    const int   tl = w;                    // local row
    const int   tg = r*RPC + w;            // global t

    // ---- load local input rows ----
    for (int i = tid; i < RPC*F; i += NTH)
        s_in[i >> 6][i & 63] = inp[(b*T + r*RPC)*F + i];
    __syncthreads();

    // ---- phase 1: h, output, score, idx_t (one warp per row) ----
    const int u0 = 2*lane, f0 = 2*lane;
    float a0 = __ldg(bk + u0), a1 = __ldg(bk + u0 + 1);
    #pragma unroll
    for (int f = 0; f < F; ++f) {
        float xin = s_in[tl][f];
        float2 kk = *(const float2*)(Wk + f*U + u0);
        a0 = fmaf(xin, kk.x, a0);
        a1 = fmaf(xin, kk.y, a1);
    }
    s_h[tl][u0]   = fast_tanh(a0);
    s_h[tl][u0+1] = fast_tanh(a1);
    __syncwarp();

    float o0 = __ldg(bv + f0), o1 = __ldg(bv + f0 + 1);
    #pragma unroll
    for (int u = 0; u < U; ++u) {
        float hv = s_h[tl][u];
        float2 vv = *(const float2*)(Wv + u*F + f0);
        o0 = fmaf(hv, vv.x, o0);
        o1 = fmaf(hv, vv.y, o1);
    }
    s_o[tl][f0] = o0; s_o[tl][f0+1] = o1;
    *(float2*)(d_out + 2*B*T + (b*T + tg)*F + f0) = make_float2(o0, o1);

    // score[f] = sum_u tanh(h[u]*out[f]*wlast)   (argmax-only path)
    const float c0 = o0*wlast, c1 = o1*wlast;
    float sc0 = 0.f, sc1 = 0.f;
    #pragma unroll
    for (int u = 0; u < U; ++u) {
        float hv = s_h[tl][u];
        sc0 += tanh_mufu(hv*c0);
        sc1 += tanh_mufu(hv*c1);
    }
    s_sc[tl][f0] = sc0; s_sc[tl][f0+1] = sc1;

    // idx_t[tg] = argmax_f (first max)
    {
        float bvv = sc0; int bf = f0;
        if (sc1 > bvv) { bvv = sc1; bf = f0 + 1; }
        #pragma unroll
        for (int o = 16; o; o >>= 1) {
            float ov = __shfl_xor_sync(0xffffffffu, bvv, o);
            int   of = __shfl_xor_sync(0xffffffffu, bf,  o);
            if (ov > bvv || (ov == bvv && of < bf)) { bvv = ov; bf = of; }
        }
        if (lane == 0) {
            uint32_t sa = smem_u32(&s_idxt[tg]);
            #pragma unroll
            for (int rr = 0; rr < CPB; ++rr) stc_s32(sa, rr, bf);
        }
    }
    __syncthreads();

    // ---- phase 2: per-f column-max candidate over local rows ----
    if (tid < F) {
        const int f = tid;
        float best = s_sc[0][f]; int bt = 0;
        #pragma unroll
        for (int t = 1; t < RPC; ++t) {
            float v = s_sc[t][f];
            if (v > best) { best = v; bt = t; }
        }
        unsigned long long c =
            ((unsigned long long)__float_as_uint(best) << 32) | (unsigned)(r*RPC + bt);
        uint32_t sa = smem_u32(&s_cand[r][f]);
        #pragma unroll
        for (int rr = 0; rr < CPB; ++rr) stc_u64(sa, rr, c);
    }
    cluster_barrier();   // A: idx_t + candidates visible everywhere

    // ---- phase 3a: idx_f -> w_s gather, wmax/wmin (replicated) ----
    if (tid < F) {
        const int f = tid;
        unsigned long long c = s_cand[0][f];
        float best = __uint_as_float((unsigned)(c >> 32));
        int   bt   = (int)(c & 0xffffffffu);
        #pragma unroll
        for (int rr = 1; rr < CPB; ++rr) {
            unsigned long long cc = s_cand[rr][f];
            float v = __uint_as_float((unsigned)(cc >> 32));
            if (v > best) { best = v; bt = (int)(cc & 0xffffffffu); }
        }
        float wv = __ldg(w_s + bt);
        float mx = wv, mn = wv;
        #pragma unroll
        for (int o = 16; o; o >>= 1) {
            mx = fmaxf(mx, __shfl_xor_sync(0xffffffffu, mx, o));
            mn = fminf(mn, __shfl_xor_sync(0xffffffffu, mn, o));
        }
        if (lane == 0) { s_wred[w][0] = mx; s_wred[w][1] = mn; }
    }
    __syncthreads();
    if (tid == 0) {
        s_wmm[0] = fmaxf(s_wred[0][0], s_wred[1][0]);
        s_wmm[1] = fminf(s_wred[0][1], s_wred[1][1]);
    }
    // amax/amin for local row tl (warp w)
    {
        float v0 = s_h[tl][s_idxt[lane]];
        float v1 = s_h[tl][s_idxt[lane + 32]];
        float mx = fmaxf(v0, v1), mn = fminf(v0, v1);
        #pragma unroll
        for (int o = 16; o; o >>= 1) {
            mx = fmaxf(mx, __shfl_xor_sync(0xffffffffu, mx, o));
            mn = fminf(mn, __shfl_xor_sync(0xffffffffu, mn, o));
        }
        if (lane == 0) { s_amax[tl] = mx; s_amin[tl] = mn; }
    }
    __syncthreads();

    // ---- phase 3b: ms for local rows ----
    {
        const float wmax = s_wmm[0], wmin = s_wmm[1];
        for (int i = tid; i < RPC*F; i += NTH) {
            const int t = i >> 6;
            const float c   = s_o[t][i & 63];
            const float amx = s_amax[t], amn = s_amin[t];
            float m = fmaxf(fmaxf(amx*wmax*c, amx*wmin*c),
                            fmaxf(amn*wmax*c, amn*wmin*c));
            s_ms[i] = fast_tanh(m);
        }
    }
    __syncthreads();

    // ---- phase 3c: logit partials over this CTA's 512-element slice ----
    {
        const float4* __restrict__ ms4 = (const float4*)s_ms;
        #pragma unroll
        for (int k = 0; k < 8; ++k) {
            const int m = w*8 + k;
            const float4* __restrict__ key4 =
                (const float4*)(mem_keys + m*TF + r*(RPC*F));
            float p0 = 0.f, p1 = 0.f, p2 = 0.f, p3 = 0.f;
            #pragma unroll
            for (int c = 0; c < 4; ++c) {
                float4 kk = key4[c*32 + lane];
                float4 mm = ms4[c*32 + lane];
                p0 = fmaf(kk.x, mm.x, p0);
                p1 = fmaf(kk.y, mm.y, p1);
                p2 = fmaf(kk.z, mm.z, p2);
                p3 = fmaf(kk.w, mm.w, p3);
            }
            float acc = (p0 + p1) + (p2 + p3);
            #pragma unroll
            for (int o = 16; o; o >>= 1)
                acc += __shfl_xor_sync(0xffffffffu, acc, o);
            if (lane == 0) s_tmp[m] = acc;
        }
    }
    __syncthreads();
    if (tid < M) {
        float v = s_tmp[tid];
        uint32_t sa = smem_u32(&s_lp[r][tid]);
        #pragma unroll
        for (int rr = 0; rr < CPB; ++rr) stc_f32(sa, rr, v);
    }
    cluster_barrier();   // B: all logit partials visible everywhere

    // ---- phase 4: softmax / importance / targets / dist ----
    float l = 0.f, e = 0.f;
    if (tid < M) {
        l = ((s_lp[0][tid] + s_lp[1][tid]) + (s_lp[2][tid] + s_lp[3][tid]))
          + ((s_lp[4][tid] + s_lp[5][tid]) + (s_lp[6][tid] + s_lp[7][tid]));
        float mx = l;
        #pragma unroll
        for (int o = 16; o; o >>= 1)
            mx = fmaxf(mx, __shfl_xor_sync(0xffffffffu, mx, o));
        if (lane == 0) s_red[w] = mx;
    }
    __syncthreads();
    const float gmax = fmaxf(s_red[0], s_red[1]);
    if (tid < M) {
        e = __expf(l - gmax);
        float s = e;
        #pragma unroll
        for (int o = 16; o; o >>= 1)
            s += __shfl_xor_sync(0xffffffffu, s, o);
        if (lane == 0) s_red[2 + w] = s;
    }
    __syncthreads();
    const float gsum = s_red[2] + s_red[3];
    const float imp  = 1.0f / gsum;          // max(attn) = exp(0)/sum
    if (tid < M) s_attn[tid] = e / gsum;
    __syncthreads();

    if (tid < F) {
        float acc = 0.f;
        #pragma unroll
        for (int mm = 0; mm < M; ++mm)
            acc = fmaf(s_attn[mm], __ldg(mem_vals + mm*F + tid), acc);
        s_tgt[tid] = acc;
    }
    __syncthreads();

    // dist for local row tl (warp w)
    {
        float d0 = s_in[tl][lane]      - s_tgt[lane];
        float d1 = s_in[tl][lane + 32] - s_tgt[lane + 32];
        float a2 = d0*d0 + d1*d1;
        #pragma unroll
        for (int o = 16; o; o >>= 1)
            a2 += __shfl_xor_sync(0xffffffffu, a2, o);
        if (lane == 0) {
            float nrm = sqrtf(a2);
            float hs  = fminf(fmaxf(0.2f*nrm + 0.5f, 0.f), 1.f);
            d_out[b*T + tg]       = 0.5f - hs;
            d_out[B*T + b*T + tg] = imp;
        }
    }
}

// =====================================================================
extern "C" void kernel_launch(void* const* d_in, const int* in_sizes, int n_in,
                              void* d_out, int out_size) {
    const float* inp      = (const float*)d_in[0];  // [B,T,F]
    const float* Wk       = (const float*)d_in[1];  // [F,U]
    const float* bk       = (const float*)d_in[2];  // [U]
    const float* Wv       = (const float*)d_in[3];  // [U,F]
    const float* bv       = (const float*)d_in[4];  // [F]
    const float* w_s      = (const float*)d_in[5];  // [S]
    const float* mem_keys = (const float*)d_in[6];  // [M, T*F]
    const float* mem_vals = (const float*)d_in[7];  // [M, F]

    fused_all<<<B*CPB, NTH>>>(inp, Wk, bk, Wv, bv, w_s, mem_keys, mem_vals,
                              (float*)d_out);
}